// round 4
// baseline (speedup 1.0000x reference)
#include <cuda_runtime.h>
#include <math.h>

#define NN 4096
#define DIMF 256
#define HIDF 64
#define NHEAD 4
#define NCLS 16

// ---------------- scratch (device globals; no allocation) ----------------
__device__ float g_h1[NN * DIMF];     // layer-1 features, concat head-major: h1[i][h*64+d]
__device__ float g_f1a[NHEAD * NN];   // f1 per head [h][i]
__device__ float g_f2a[NHEAD * NN];   // f2 per head [h][i]
__device__ float g_hcat[NN * DIMF];   // after attention + ELU
__device__ float g_h2[NN * NCLS];     // layer-2 features
__device__ float g_f1b[NN];
__device__ float g_f2b[NN];

// ---------------- K1: h1 = x @ W1^T  (4096x256 @ 256x256) ----------------
// BM=64, BN=64, BK=16, 256 threads, 4x4 micro-tile per thread.
__global__ void k1_gemm(const float* __restrict__ A, const float* __restrict__ W) {
    __shared__ __align__(16) float As[16][68];
    __shared__ __align__(16) float Bs[16][68];
    int t = threadIdx.x;
    int tx = t & 15, ty = t >> 4;
    int bm = blockIdx.x * 64;
    int bn = blockIdx.y * 64;

    float acc[4][4];
#pragma unroll
    for (int i = 0; i < 4; i++)
#pragma unroll
        for (int j = 0; j < 4; j++) acc[i][j] = 0.f;

    int lr = t >> 2;          // 0..63
    int lk = (t & 3) * 4;     // 0,4,8,12

    for (int k0 = 0; k0 < DIMF; k0 += 16) {
        float4 av = *(const float4*)(A + (bm + lr) * DIMF + k0 + lk);
        float4 bv = *(const float4*)(W + (bn + lr) * DIMF + k0 + lk);
        As[lk + 0][lr] = av.x; As[lk + 1][lr] = av.y;
        As[lk + 2][lr] = av.z; As[lk + 3][lr] = av.w;
        Bs[lk + 0][lr] = bv.x; Bs[lk + 1][lr] = bv.y;
        Bs[lk + 2][lr] = bv.z; Bs[lk + 3][lr] = bv.w;
        __syncthreads();
#pragma unroll
        for (int k = 0; k < 16; k++) {
            float4 a4 = *(const float4*)&As[k][ty * 4];
            float4 b4 = *(const float4*)&Bs[k][tx * 4];
            float a[4] = {a4.x, a4.y, a4.z, a4.w};
            float b[4] = {b4.x, b4.y, b4.z, b4.w};
#pragma unroll
            for (int i = 0; i < 4; i++)
#pragma unroll
                for (int j = 0; j < 4; j++) acc[i][j] += a[i] * b[j];
        }
        __syncthreads();
    }
#pragma unroll
    for (int i = 0; i < 4; i++) {
        float4 o = make_float4(acc[i][0], acc[i][1], acc[i][2], acc[i][3]);
        *(float4*)&g_h1[(bm + ty * 4 + i) * DIMF + bn + tx * 4] = o;
    }
}

// ---------------- K2: f1/f2 per head ----------------
__global__ void k2_f(const float* __restrict__ a1, const float* __restrict__ a2) {
    __shared__ float s1[256], s2[256];
    int i = blockIdx.x;
    int t = threadIdx.x;
    float h = g_h1[i * DIMF + t];
    s1[t] = h * a1[t];
    s2[t] = h * a2[t];
    __syncthreads();
    for (int st = 32; st > 0; st >>= 1) {
        if ((t & 63) < st) { s1[t] += s1[t + st]; s2[t] += s2[t + st]; }
        __syncthreads();
    }
    if ((t & 63) == 0) {
        int hh = t >> 6;
        g_f1a[hh * NN + i] = s1[t];
        g_f2a[hh * NN + i] = s2[t];
    }
}

// ---------------- K3: layer-1 attention (fused mask+lrelu+exp+softmax+matmul+ELU) ----
// Block = 256 threads = 256 dims; handles 16 rows; chunks of 64 j.
#define R1 16
#define CH1 64
__global__ void k3_attn1(const int* __restrict__ adj) {
    __shared__ float f1s[R1][NHEAD];
    __shared__ int   adjs[R1][CH1];
    __shared__ float f2s[NHEAD][CH1];
    __shared__ __align__(16) float ps[CH1 * 68];   // [jj][h*16+r], row stride 68
    __shared__ float ss[R1 * NHEAD];               // [h*16+r]

    int t = threadIdx.x;
    int i0 = blockIdx.x * R1;
    if (t < R1 * NHEAD) {
        int r = t >> 2, h = t & 3;
        f1s[r][h] = g_f1a[h * NN + i0 + r];
        ss[t] = 0.f;
    }
    float acc[R1];
#pragma unroll
    for (int r = 0; r < R1; r++) acc[r] = 0.f;

    const int d = t;
    const int h16 = (d >> 6) * 16;   // head group offset into ps rows

    for (int j0 = 0; j0 < NN; j0 += CH1) {
        __syncthreads();
        // load adjacency chunk: 16x64 ints
#pragma unroll
        for (int u = 0; u < 4; u++) {
            int idx = t + u * 256;
            int r = idx >> 6, jj = idx & 63;
            adjs[r][jj] = adj[(i0 + r) * NN + j0 + jj];
        }
        // load f2 chunk: 4x64
        { int h = t >> 6, jj = t & 63; f2s[h][jj] = g_f2a[h * NN + j0 + jj]; }
        __syncthreads();
        // compute p: thread grp=h handles all 16 rows for its jj
        {
            int jj = t & 63;
            int hh = t >> 6;
            float f2v = f2s[hh][jj];
            int adjcol[1];
            (void)adjcol;
#pragma unroll
            for (int r = 0; r < R1; r++) {
                float z = f1s[r][hh] + f2v;
                float e = z > 0.f ? z : 0.01f * z;
                float p = (adjs[r][jj] != 0 && e != 0.f) ? __expf(e) : 0.f;
                ps[jj * 68 + hh * 16 + r] = p;
            }
        }
        __syncthreads();
        // FMA phase: out[i0+r][d] += p[r] * h1[j][d]
#pragma unroll 4
        for (int jj = 0; jj < CH1; jj++) {
            float v = __ldg(&g_h1[(j0 + jj) * DIMF + d]);
            const float* prow = &ps[jj * 68 + h16];
            float4 p0 = *(const float4*)&prow[0];
            float4 p1 = *(const float4*)&prow[4];
            float4 p2 = *(const float4*)&prow[8];
            float4 p3 = *(const float4*)&prow[12];
            acc[0]  += p0.x * v; acc[1]  += p0.y * v; acc[2]  += p0.z * v; acc[3]  += p0.w * v;
            acc[4]  += p1.x * v; acc[5]  += p1.y * v; acc[6]  += p1.z * v; acc[7]  += p1.w * v;
            acc[8]  += p2.x * v; acc[9]  += p2.y * v; acc[10] += p2.z * v; acc[11] += p2.w * v;
            acc[12] += p3.x * v; acc[13] += p3.y * v; acc[14] += p3.z * v; acc[15] += p3.w * v;
        }
        // softmax denominator partials (threads 0..63 own one (h,r) each)
        if (t < 64) {
            float sp = 0.f;
#pragma unroll
            for (int jj = 0; jj < CH1; jj++) sp += ps[jj * 68 + t];
            ss[t] += sp;
        }
    }
    __syncthreads();
    // normalize + ELU + store
#pragma unroll
    for (int r = 0; r < R1; r++) {
        float o = acc[r] / ss[h16 + r];
        o = o > 0.f ? o : expm1f(o);
        g_hcat[(i0 + r) * DIMF + d] = o;
    }
}

// ---------------- K4: h2 = hcat @ W2^T and f1b/f2b ----------------
__global__ void k4_l2(const float* __restrict__ W2, const float* __restrict__ a1,
                      const float* __restrict__ a2) {
    __shared__ float W2s[NCLS][DIMF];
    __shared__ float a1s[NCLS], a2s[NCLS];
    int t = threadIdx.x;
    for (int u = t; u < NCLS * DIMF; u += 256) W2s[u >> 8][u & 255] = W2[u];
    if (t < NCLS) { a1s[t] = a1[t]; a2s[t] = a2[t]; }
    __syncthreads();

    int w = t >> 5, l = t & 31;
    int i = blockIdx.x * 8 + w;
    float hreg[8];
#pragma unroll
    for (int u = 0; u < 8; u++) hreg[u] = g_hcat[i * DIMF + l + u * 32];

    float myh2 = 0.f;
#pragma unroll
    for (int c = 0; c < NCLS; c++) {
        float s = 0.f;
#pragma unroll
        for (int u = 0; u < 8; u++) s += hreg[u] * W2s[c][l + u * 32];
#pragma unroll
        for (int o = 16; o > 0; o >>= 1) s += __shfl_xor_sync(0xffffffffu, s, o);
        if (l == c) myh2 = s;
    }
    if (l < NCLS) g_h2[i * NCLS + l] = myh2;

    float v1 = (l < NCLS) ? myh2 * a1s[l] : 0.f;
    float v2 = (l < NCLS) ? myh2 * a2s[l] : 0.f;
#pragma unroll
    for (int o = 8; o > 0; o >>= 1) {
        v1 += __shfl_xor_sync(0xffffffffu, v1, o);
        v2 += __shfl_xor_sync(0xffffffffu, v2, o);
    }
    if (l == 0) { g_f1b[i] = v1; g_f2b[i] = v2; }
}

// ---------------- K5: layer-2 attention -> logits ----------------
#define R2 16
#define CH2 64
__global__ void k5_attn2(const int* __restrict__ adj, float* __restrict__ out) {
    __shared__ float f1s[R2];
    __shared__ int   adjs[R2][CH2];
    __shared__ float f2s[CH2];
    __shared__ float ps[R2][CH2 + 1];
    __shared__ float h2s[CH2 * NCLS];
    __shared__ float ss[R2];

    int t = threadIdx.x;
    int i0 = blockIdx.x * R2;
    if (t < R2) { f1s[t] = g_f1b[i0 + t]; ss[t] = 0.f; }
    int c = t & 15, rmy = t >> 4;
    float acc = 0.f;

    for (int j0 = 0; j0 < NN; j0 += CH2) {
        __syncthreads();
#pragma unroll
        for (int u = 0; u < 4; u++) {
            int idx = t + u * 256;
            int r = idx >> 6, jj = idx & 63;
            adjs[r][jj] = adj[(i0 + r) * NN + j0 + jj];
        }
        if (t < CH2) f2s[t] = g_f2b[j0 + t];
#pragma unroll
        for (int u = 0; u < 4; u++) {
            int idx = t + u * 256;   // 0..1023 = CH2*NCLS
            h2s[idx] = g_h2[j0 * NCLS + idx];
        }
        __syncthreads();
        {
            int jj = t & 63;
            int grp = t >> 6;
            float f2v = f2s[jj];
#pragma unroll
            for (int it = 0; it < 4; it++) {
                int r = grp * 4 + it;
                float z = f1s[r] + f2v;
                float e = z > 0.f ? z : 0.01f * z;
                ps[r][jj] = (adjs[r][jj] != 0 && e != 0.f) ? __expf(e) : 0.f;
            }
        }
        __syncthreads();
#pragma unroll 8
        for (int jj = 0; jj < CH2; jj++) {
            acc += ps[rmy][jj] * h2s[jj * NCLS + c];
        }
        if (t < R2) {
            float sp = 0.f;
#pragma unroll
            for (int jj = 0; jj < CH2; jj++) sp += ps[t][jj];
            ss[t] += sp;
        }
    }
    __syncthreads();
    out[(i0 + rmy) * NCLS + c] = acc / ss[rmy];
}

// ---------------- launcher ----------------
extern "C" void kernel_launch(void* const* d_in, const int* in_sizes, int n_in,
                              void* d_out, int out_size) {
    const float* x   = (const float*)d_in[0];
    const int*   adj = (const int*)d_in[1];
    const float* W1  = (const float*)d_in[2];
    const float* a11 = (const float*)d_in[3];
    const float* a21 = (const float*)d_in[4];
    const float* W2  = (const float*)d_in[5];
    const float* a12 = (const float*)d_in[6];
    const float* a22 = (const float*)d_in[7];
    float* out = (float*)d_out;

    k1_gemm<<<dim3(64, 4), 256>>>(x, W1);
    k2_f<<<NN, 256>>>(a11, a21);
    k3_attn1<<<NN / R1, 256>>>(adj);
    k4_l2<<<NN / 8, 256>>>(W2, a12, a22);
    k5_attn2<<<NN / R2, 256>>>(adj, out);
}

// round 9
// speedup vs baseline: 1.0348x; 1.0348x over previous
#include <cuda_runtime.h>
#include <math.h>

#define NN 4096
#define DIMF 256
#define HIDF 64
#define NHEAD 4
#define NCLS 16

// ---------------- scratch (device globals; no allocation) ----------------
__device__ float g_h1[NN * DIMF];     // layer-1 features, concat head-major: h1[i][h*64+d]
__device__ float g_f1a[NHEAD * NN];   // f1 per head [h][i]
__device__ float g_f2a[NHEAD * NN];   // f2 per head [h][i]
__device__ float g_hcat[NN * DIMF];   // after attention + ELU
__device__ float g_h2[NN * NCLS];     // layer-2 features
__device__ float g_f1b[NN];
__device__ float g_f2b[NN];

// ---------------- fast exp: FFMA/ALU only, no MUFU ----------------
// exp(z) = 2^(z*log2e) = 2^n * 2^r,  n = rint(t), r = t-n in [-0.5, 0.5].
// n extracted via the 1.5*2^23 magic-add; 2^r via degree-6 Taylor (rel err ~1e-7).
__device__ __forceinline__ float fast_exp(float z) {
    z = fminf(fmaxf(z, -80.0f), 80.0f);
    float t  = z * 1.4426950408889634f;
    float tf = t + 12582912.0f;                  // round-to-nearest-int in low bits
    float fn = tf - 12582912.0f;                 // fn = rint(t)
    float r  = t - fn;                           // r in [-0.5, 0.5]
    int   n  = __float_as_int(tf) - 0x4B400000;  // signed integer rint(t)
    float scale = __int_as_float((n + 127) << 23);   // 2^n
    float p;
    p = 1.5401354e-4f;
    p = fmaf(p, r, 1.3333558e-3f);
    p = fmaf(p, r, 9.6181291e-3f);
    p = fmaf(p, r, 5.5504109e-2f);
    p = fmaf(p, r, 2.4022651e-1f);
    p = fmaf(p, r, 6.9314718e-1f);
    p = fmaf(p, r, 1.0f);
    return p * scale;
}

// ---------------- K1: h1 = x @ W1^T  (4096x256 @ 256x256) ----------------
// BM=64, BN=64, BK=16, 256 threads, 4x4 micro-tile per thread.
__global__ void k1_gemm(const float* __restrict__ A, const float* __restrict__ W) {
    __shared__ __align__(16) float As[16][68];
    __shared__ __align__(16) float Bs[16][68];
    int t = threadIdx.x;
    int tx = t & 15, ty = t >> 4;
    int bm = blockIdx.x * 64;
    int bn = blockIdx.y * 64;

    float acc[4][4];
#pragma unroll
    for (int i = 0; i < 4; i++)
#pragma unroll
        for (int j = 0; j < 4; j++) acc[i][j] = 0.f;

    int lr = t >> 2;          // 0..63
    int lk = (t & 3) * 4;     // 0,4,8,12

    for (int k0 = 0; k0 < DIMF; k0 += 16) {
        float4 av = *(const float4*)(A + (bm + lr) * DIMF + k0 + lk);
        float4 bv = *(const float4*)(W + (bn + lr) * DIMF + k0 + lk);
        As[lk + 0][lr] = av.x; As[lk + 1][lr] = av.y;
        As[lk + 2][lr] = av.z; As[lk + 3][lr] = av.w;
        Bs[lk + 0][lr] = bv.x; Bs[lk + 1][lr] = bv.y;
        Bs[lk + 2][lr] = bv.z; Bs[lk + 3][lr] = bv.w;
        __syncthreads();
#pragma unroll
        for (int k = 0; k < 16; k++) {
            float4 a4 = *(const float4*)&As[k][ty * 4];
            float4 b4 = *(const float4*)&Bs[k][tx * 4];
            float a[4] = {a4.x, a4.y, a4.z, a4.w};
            float b[4] = {b4.x, b4.y, b4.z, b4.w};
#pragma unroll
            for (int i = 0; i < 4; i++)
#pragma unroll
                for (int j = 0; j < 4; j++) acc[i][j] += a[i] * b[j];
        }
        __syncthreads();
    }
#pragma unroll
    for (int i = 0; i < 4; i++) {
        float4 o = make_float4(acc[i][0], acc[i][1], acc[i][2], acc[i][3]);
        *(float4*)&g_h1[(bm + ty * 4 + i) * DIMF + bn + tx * 4] = o;
    }
}

// ---------------- K2: f1/f2 per head ----------------
__global__ void k2_f(const float* __restrict__ a1, const float* __restrict__ a2) {
    __shared__ float s1[256], s2[256];
    int i = blockIdx.x;
    int t = threadIdx.x;
    float h = g_h1[i * DIMF + t];
    s1[t] = h * a1[t];
    s2[t] = h * a2[t];
    __syncthreads();
    for (int st = 32; st > 0; st >>= 1) {
        if ((t & 63) < st) { s1[t] += s1[t + st]; s2[t] += s2[t + st]; }
        __syncthreads();
    }
    if ((t & 63) == 0) {
        int hh = t >> 6;
        g_f1a[hh * NN + i] = s1[t];
        g_f2a[hh * NN + i] = s2[t];
    }
}

// ---------------- K3: layer-1 attention (fused mask+lrelu+exp+softmax+matmul+ELU) ----
// Block = 256 threads = 256 dims; handles 16 rows; chunks of 64 j.
#define R1 16
#define CH1 64
__global__ void k3_attn1(const int* __restrict__ adj) {
    __shared__ float f1s[R1][NHEAD];
    __shared__ int   adjs[R1][CH1];
    __shared__ float f2s[NHEAD][CH1];
    __shared__ __align__(16) float ps[CH1 * 68];   // [jj][h*16+r], row stride 68
    __shared__ float ss[R1 * NHEAD];               // [h*16+r]

    int t = threadIdx.x;
    int i0 = blockIdx.x * R1;
    if (t < R1 * NHEAD) {
        int r = t >> 2, h = t & 3;
        f1s[r][h] = g_f1a[h * NN + i0 + r];
        ss[t] = 0.f;
    }
    float acc[R1];
#pragma unroll
    for (int r = 0; r < R1; r++) acc[r] = 0.f;

    const int d = t;
    const int h16 = (d >> 6) * 16;   // head group offset into ps rows

    for (int j0 = 0; j0 < NN; j0 += CH1) {
        __syncthreads();
        // load adjacency chunk: 16x64 ints
#pragma unroll
        for (int u = 0; u < 4; u++) {
            int idx = t + u * 256;
            int r = idx >> 6, jj = idx & 63;
            adjs[r][jj] = adj[(i0 + r) * NN + j0 + jj];
        }
        // load f2 chunk: 4x64
        { int h = t >> 6, jj = t & 63; f2s[h][jj] = g_f2a[h * NN + j0 + jj]; }
        __syncthreads();
        // compute p: thread grp=h handles all 16 rows for its jj (no MUFU)
        {
            int jj = t & 63;
            int hh = t >> 6;
            float f2v = f2s[hh][jj];
#pragma unroll
            for (int r = 0; r < R1; r++) {
                float z = f1s[r][hh] + f2v;
                float e = z > 0.f ? z : 0.01f * z;
                float pv = fast_exp(e);
                float p = (adjs[r][jj] != 0 && e != 0.f) ? pv : 0.f;
                ps[jj * 68 + hh * 16 + r] = p;
            }
        }
        __syncthreads();
        // FMA phase: out[i0+r][d] += p[r] * h1[j][d]
#pragma unroll 4
        for (int jj = 0; jj < CH1; jj++) {
            float v = __ldg(&g_h1[(j0 + jj) * DIMF + d]);
            const float* prow = &ps[jj * 68 + h16];
            float4 p0 = *(const float4*)&prow[0];
            float4 p1 = *(const float4*)&prow[4];
            float4 p2 = *(const float4*)&prow[8];
            float4 p3 = *(const float4*)&prow[12];
            acc[0]  += p0.x * v; acc[1]  += p0.y * v; acc[2]  += p0.z * v; acc[3]  += p0.w * v;
            acc[4]  += p1.x * v; acc[5]  += p1.y * v; acc[6]  += p1.z * v; acc[7]  += p1.w * v;
            acc[8]  += p2.x * v; acc[9]  += p2.y * v; acc[10] += p2.z * v; acc[11] += p2.w * v;
            acc[12] += p3.x * v; acc[13] += p3.y * v; acc[14] += p3.z * v; acc[15] += p3.w * v;
        }
        // softmax denominator partials (threads 0..63 own one (h,r) each)
        if (t < 64) {
            float sp = 0.f;
#pragma unroll
            for (int jj = 0; jj < CH1; jj++) sp += ps[jj * 68 + t];
            ss[t] += sp;
        }
    }
    __syncthreads();
    // normalize + ELU + store
#pragma unroll
    for (int r = 0; r < R1; r++) {
        float o = acc[r] / ss[h16 + r];
        o = o > 0.f ? o : expm1f(o);
        g_hcat[(i0 + r) * DIMF + d] = o;
    }
}

// ---------------- K4: h2 = hcat @ W2^T and f1b/f2b ----------------
__global__ void k4_l2(const float* __restrict__ W2, const float* __restrict__ a1,
                      const float* __restrict__ a2) {
    __shared__ float W2s[NCLS][DIMF];
    __shared__ float a1s[NCLS], a2s[NCLS];
    int t = threadIdx.x;
    for (int u = t; u < NCLS * DIMF; u += 256) W2s[u >> 8][u & 255] = W2[u];
    if (t < NCLS) { a1s[t] = a1[t]; a2s[t] = a2[t]; }
    __syncthreads();

    int w = t >> 5, l = t & 31;
    int i = blockIdx.x * 8 + w;
    float hreg[8];
#pragma unroll
    for (int u = 0; u < 8; u++) hreg[u] = g_hcat[i * DIMF + l + u * 32];

    float myh2 = 0.f;
#pragma unroll
    for (int c = 0; c < NCLS; c++) {
        float s = 0.f;
#pragma unroll
        for (int u = 0; u < 8; u++) s += hreg[u] * W2s[c][l + u * 32];
#pragma unroll
        for (int o = 16; o > 0; o >>= 1) s += __shfl_xor_sync(0xffffffffu, s, o);
        if (l == c) myh2 = s;
    }
    if (l < NCLS) g_h2[i * NCLS + l] = myh2;

    float v1 = (l < NCLS) ? myh2 * a1s[l] : 0.f;
    float v2 = (l < NCLS) ? myh2 * a2s[l] : 0.f;
#pragma unroll
    for (int o = 8; o > 0; o >>= 1) {
        v1 += __shfl_xor_sync(0xffffffffu, v1, o);
        v2 += __shfl_xor_sync(0xffffffffu, v2, o);
    }
    if (l == 0) { g_f1b[i] = v1; g_f2b[i] = v2; }
}

// ---------------- K5: layer-2 attention -> logits ----------------
#define R2 16
#define CH2 64
__global__ void k5_attn2(const int* __restrict__ adj, float* __restrict__ out) {
    __shared__ float f1s[R2];
    __shared__ int   adjs[R2][CH2];
    __shared__ float f2s[CH2];
    __shared__ float ps[R2][CH2 + 1];
    __shared__ float h2s[CH2 * NCLS];
    __shared__ float ss[R2];

    int t = threadIdx.x;
    int i0 = blockIdx.x * R2;
    if (t < R2) { f1s[t] = g_f1b[i0 + t]; ss[t] = 0.f; }
    int c = t & 15, rmy = t >> 4;
    float acc = 0.f;

    for (int j0 = 0; j0 < NN; j0 += CH2) {
        __syncthreads();
#pragma unroll
        for (int u = 0; u < 4; u++) {
            int idx = t + u * 256;
            int r = idx >> 6, jj = idx & 63;
            adjs[r][jj] = adj[(i0 + r) * NN + j0 + jj];
        }
        if (t < CH2) f2s[t] = g_f2b[j0 + t];
#pragma unroll
        for (int u = 0; u < 4; u++) {
            int idx = t + u * 256;   // 0..1023 = CH2*NCLS
            h2s[idx] = g_h2[j0 * NCLS + idx];
        }
        __syncthreads();
        {
            int jj = t & 63;
            int grp = t >> 6;
            float f2v = f2s[jj];
#pragma unroll
            for (int it = 0; it < 4; it++) {
                int r = grp * 4 + it;
                float z = f1s[r] + f2v;
                float e = z > 0.f ? z : 0.01f * z;
                float pv = fast_exp(e);
                ps[r][jj] = (adjs[r][jj] != 0 && e != 0.f) ? pv : 0.f;
            }
        }
        __syncthreads();
#pragma unroll 8
        for (int jj = 0; jj < CH2; jj++) {
            acc += ps[rmy][jj] * h2s[jj * NCLS + c];
        }
        if (t < R2) {
            float sp = 0.f;
#pragma unroll
            for (int jj = 0; jj < CH2; jj++) sp += ps[t][jj];
            ss[t] += sp;
        }
    }
    __syncthreads();
    out[(i0 + rmy) * NCLS + c] = acc / ss[rmy];
}

// ---------------- launcher ----------------
extern "C" void kernel_launch(void* const* d_in, const int* in_sizes, int n_in,
                              void* d_out, int out_size) {
    const float* x   = (const float*)d_in[0];
    const int*   adj = (const int*)d_in[1];
    const float* W1  = (const float*)d_in[2];
    const float* a11 = (const float*)d_in[3];
    const float* a21 = (const float*)d_in[4];
    const float* W2  = (const float*)d_in[5];
    const float* a12 = (const float*)d_in[6];
    const float* a22 = (const float*)d_in[7];
    float* out = (float*)d_out;

    k1_gemm<<<dim3(64, 4), 256>>>(x, W1);
    k2_f<<<NN, 256>>>(a11, a21);
    k3_attn1<<<NN / R1, 256>>>(adj);
    k4_l2<<<NN / 8, 256>>>(W2, a12, a22);
    k5_attn2<<<NN / R2, 256>>>(adj, out);
}

// round 11
// speedup vs baseline: 1.0913x; 1.0546x over previous
#include <cuda_runtime.h>
#include <math.h>

#define NN 4096
#define DIMF 256
#define HIDF 64
#define NHEAD 4
#define NCLS 16
#define JSPLIT 2

// ---------------- scratch (device globals; no allocation) ----------------
__device__ float g_h1[NN * DIMF];           // layer-1 features [i][h*64+d]
__device__ float g_f1a[NHEAD * NN];         // f1 per head [h][i]
__device__ float g_f2a[NHEAD * NN];         // f2 per head [h][i]
__device__ float g_pacc[JSPLIT * NN * DIMF];   // partial attention accumulators
__device__ float g_pss[JSPLIT * NHEAD * NN];   // partial softmax denominators [js][h][i]
__device__ float g_hcat[NN * DIMF];         // after attention + ELU
__device__ float g_h2[NN * NCLS];           // layer-2 features
__device__ float g_f1b[NN];
__device__ float g_f2b[NN];

// ---------------- fast exp: FFMA/ALU only, no MUFU ----------------
__device__ __forceinline__ float fast_exp(float z) {
    z = fminf(fmaxf(z, -80.0f), 80.0f);
    float t  = z * 1.4426950408889634f;
    float tf = t + 12582912.0f;
    float fn = tf - 12582912.0f;
    float r  = t - fn;
    int   n  = __float_as_int(tf) - 0x4B400000;
    float scale = __int_as_float((n + 127) << 23);
    float p;
    p = 1.5401354e-4f;
    p = fmaf(p, r, 1.3333558e-3f);
    p = fmaf(p, r, 9.6181291e-3f);
    p = fmaf(p, r, 5.5504109e-2f);
    p = fmaf(p, r, 2.4022651e-1f);
    p = fmaf(p, r, 6.9314718e-1f);
    p = fmaf(p, r, 1.0f);
    return p * scale;
}

// ---------------- packed f32x2 helpers ----------------
__device__ __forceinline__ void ffma2(unsigned long long& acc,
                                      unsigned long long a,
                                      unsigned long long b) {
    asm("fma.rn.f32x2 %0, %1, %2, %0;" : "+l"(acc) : "l"(a), "l"(b));
}
__device__ __forceinline__ unsigned long long pack2(float v) {
    unsigned long long r;
    unsigned int u = __float_as_uint(v);
    asm("mov.b64 %0, {%1, %1};" : "=l"(r) : "r"(u));
    return r;
}
__device__ __forceinline__ void unpack2(unsigned long long v, float& lo, float& hi) {
    unsigned int a, b;
    asm("mov.b64 {%0, %1}, %2;" : "=r"(a), "=r"(b) : "l"(v));
    lo = __uint_as_float(a); hi = __uint_as_float(b);
}

// ---------------- K1: h1 = x @ W1^T ----------------
__global__ void k1_gemm(const float* __restrict__ A, const float* __restrict__ W) {
    __shared__ __align__(16) float As[16][68];
    __shared__ __align__(16) float Bs[16][68];
    int t = threadIdx.x;
    int tx = t & 15, ty = t >> 4;
    int bm = blockIdx.x * 64;
    int bn = blockIdx.y * 64;

    float acc[4][4];
#pragma unroll
    for (int i = 0; i < 4; i++)
#pragma unroll
        for (int j = 0; j < 4; j++) acc[i][j] = 0.f;

    int lr = t >> 2;
    int lk = (t & 3) * 4;

    for (int k0 = 0; k0 < DIMF; k0 += 16) {
        float4 av = *(const float4*)(A + (bm + lr) * DIMF + k0 + lk);
        float4 bv = *(const float4*)(W + (bn + lr) * DIMF + k0 + lk);
        As[lk + 0][lr] = av.x; As[lk + 1][lr] = av.y;
        As[lk + 2][lr] = av.z; As[lk + 3][lr] = av.w;
        Bs[lk + 0][lr] = bv.x; Bs[lk + 1][lr] = bv.y;
        Bs[lk + 2][lr] = bv.z; Bs[lk + 3][lr] = bv.w;
        __syncthreads();
#pragma unroll
        for (int k = 0; k < 16; k++) {
            float4 a4 = *(const float4*)&As[k][ty * 4];
            float4 b4 = *(const float4*)&Bs[k][tx * 4];
            float a[4] = {a4.x, a4.y, a4.z, a4.w};
            float b[4] = {b4.x, b4.y, b4.z, b4.w};
#pragma unroll
            for (int i = 0; i < 4; i++)
#pragma unroll
                for (int j = 0; j < 4; j++) acc[i][j] += a[i] * b[j];
        }
        __syncthreads();
    }
#pragma unroll
    for (int i = 0; i < 4; i++) {
        float4 o = make_float4(acc[i][0], acc[i][1], acc[i][2], acc[i][3]);
        *(float4*)&g_h1[(bm + ty * 4 + i) * DIMF + bn + tx * 4] = o;
    }
}

// ---------------- K2: f1/f2 per head ----------------
__global__ void k2_f(const float* __restrict__ a1, const float* __restrict__ a2) {
    __shared__ float s1[256], s2[256];
    int i = blockIdx.x;
    int t = threadIdx.x;
    float h = g_h1[i * DIMF + t];
    s1[t] = h * a1[t];
    s2[t] = h * a2[t];
    __syncthreads();
    for (int st = 32; st > 0; st >>= 1) {
        if ((t & 63) < st) { s1[t] += s1[t + st]; s2[t] += s2[t + st]; }
        __syncthreads();
    }
    if ((t & 63) == 0) {
        int hh = t >> 6;
        g_f1a[hh * NN + i] = s1[t];
        g_f2a[hh * NN + i] = s2[t];
    }
}

// ---------------- K3: layer-1 attention, j-split, f32x2 FMA ----------------
// grid (NN/R1, JSPLIT), 256 threads. Each block: 16 rows x 2048 j's.
#define R1 16
#define CH1 64
#define JCHUNKS (NN / JSPLIT / CH1)   // 32
__global__ void k3_attn1(const int* __restrict__ adj) {
    __shared__ float f1s[R1][NHEAD];
    __shared__ int   adjs[R1][CH1];
    __shared__ float f2s[NHEAD][CH1];
    __shared__ __align__(16) float ps[CH1 * 68];   // [jj][h*16+r], stride 68

    int t = threadIdx.x;
    int i0 = blockIdx.x * R1;
    int js = blockIdx.y;
    int jbase = js * (NN / JSPLIT);

    if (t < R1 * NHEAD) {
        int r = t >> 2, h = t & 3;
        f1s[r][h] = g_f1a[h * NN + i0 + r];
    }

    unsigned long long acc2[8];
#pragma unroll
    for (int j = 0; j < 8; j++) acc2[j] = 0ull;
    float sacc[R1];                 // per-thread softmax-denominator partials (own jj lane)
#pragma unroll
    for (int r = 0; r < R1; r++) sacc[r] = 0.f;

    const int d = t;
    const int h16 = (d >> 6) * 16;
    const int jj = t & 63;
    const int hh = t >> 6;

    for (int c = 0; c < JCHUNKS; c++) {
        int j0 = jbase + c * CH1;
        __syncthreads();
        // adjacency chunk 16x64
#pragma unroll
        for (int u = 0; u < 4; u++) {
            int idx = t + u * 256;
            int r = idx >> 6, j2 = idx & 63;
            adjs[r][j2] = adj[(i0 + r) * NN + j0 + j2];
        }
        // f2 chunk 4x64
        f2s[hh][jj] = g_f2a[hh * NN + j0 + jj];
        __syncthreads();
        // p computation + in-register denominator accumulation
        {
            float f2v = f2s[hh][jj];
#pragma unroll
            for (int r = 0; r < R1; r++) {
                float z = f1s[r][hh] + f2v;
                float e = z > 0.f ? z : 0.01f * z;
                float pv = fast_exp(e);
                float p = (adjs[r][jj] != 0 && e != 0.f) ? pv : 0.f;
                ps[jj * 68 + hh * 16 + r] = p;
                sacc[r] += p;
            }
        }
        __syncthreads();
        // FMA phase with packed f32x2: out[i0+r][d] += p[r]*h1[j][d]
#pragma unroll 4
        for (int j2 = 0; j2 < CH1; j2++) {
            float v = __ldg(&g_h1[(j0 + j2) * DIMF + d]);
            unsigned long long v2 = pack2(v);
            const ulonglong2* prow = (const ulonglong2*)&ps[j2 * 68 + h16];
            ulonglong2 qa = prow[0];
            ulonglong2 qb = prow[1];
            ulonglong2 qc = prow[2];
            ulonglong2 qd = prow[3];
            ffma2(acc2[0], qa.x, v2); ffma2(acc2[1], qa.y, v2);
            ffma2(acc2[2], qb.x, v2); ffma2(acc2[3], qb.y, v2);
            ffma2(acc2[4], qc.x, v2); ffma2(acc2[5], qc.y, v2);
            ffma2(acc2[6], qd.x, v2); ffma2(acc2[7], qd.y, v2);
        }
    }

    // store partial accumulators
#pragma unroll
    for (int j = 0; j < 8; j++) {
        float lo, hi;
        unpack2(acc2[j], lo, hi);
        g_pacc[(size_t)js * NN * DIMF + (i0 + 2 * j) * DIMF + d]     = lo;
        g_pacc[(size_t)js * NN * DIMF + (i0 + 2 * j + 1) * DIMF + d] = hi;
    }

    // reduce sacc over the 64 jj-lanes per head (reuse ps storage)
    __syncthreads();
#pragma unroll
    for (int r = 0; r < R1; r++) ps[t * 16 + r] = sacc[r];
    __syncthreads();
    if (t < 64) {
        int h = t >> 4, r = t & 15;
        float s = 0.f;
#pragma unroll
        for (int j2 = 0; j2 < 64; j2++) s += ps[(h * 64 + j2) * 16 + r];
        g_pss[js * NHEAD * NN + h * NN + i0 + r] = s;
    }
}

// ---------------- K3b: combine partials, normalize, ELU ----------------
__global__ void k3b_combine() {
    int i = blockIdx.x;
    int d = threadIdx.x;
    int h = d >> 6;
    float s = g_pss[h * NN + i] + g_pss[NHEAD * NN + h * NN + i];
    float a = g_pacc[(size_t)i * DIMF + d] + g_pacc[(size_t)NN * DIMF + i * DIMF + d];
    float o = a / s;
    o = o > 0.f ? o : expm1f(o);
    g_hcat[i * DIMF + d] = o;
}

// ---------------- K4: h2 = hcat @ W2^T and f1b/f2b ----------------
__global__ void k4_l2(const float* __restrict__ W2, const float* __restrict__ a1,
                      const float* __restrict__ a2) {
    __shared__ float W2s[NCLS][DIMF];
    __shared__ float a1s[NCLS], a2s[NCLS];
    int t = threadIdx.x;
    for (int u = t; u < NCLS * DIMF; u += 256) W2s[u >> 8][u & 255] = W2[u];
    if (t < NCLS) { a1s[t] = a1[t]; a2s[t] = a2[t]; }
    __syncthreads();

    int w = t >> 5, l = t & 31;
    int i = blockIdx.x * 8 + w;
    float hreg[8];
#pragma unroll
    for (int u = 0; u < 8; u++) hreg[u] = g_hcat[i * DIMF + l + u * 32];

    float myh2 = 0.f;
#pragma unroll
    for (int c = 0; c < NCLS; c++) {
        float s = 0.f;
#pragma unroll
        for (int u = 0; u < 8; u++) s += hreg[u] * W2s[c][l + u * 32];
#pragma unroll
        for (int o = 16; o > 0; o >>= 1) s += __shfl_xor_sync(0xffffffffu, s, o);
        if (l == c) myh2 = s;
    }
    if (l < NCLS) g_h2[i * NCLS + l] = myh2;

    float v1 = (l < NCLS) ? myh2 * a1s[l] : 0.f;
    float v2 = (l < NCLS) ? myh2 * a2s[l] : 0.f;
#pragma unroll
    for (int o = 8; o > 0; o >>= 1) {
        v1 += __shfl_xor_sync(0xffffffffu, v1, o);
        v2 += __shfl_xor_sync(0xffffffffu, v2, o);
    }
    if (l == 0) { g_f1b[i] = v1; g_f2b[i] = v2; }
}

// ---------------- K5: layer-2 attention -> logits ----------------
#define R2 16
#define CH2 64
__global__ void k5_attn2(const int* __restrict__ adj, float* __restrict__ out) {
    __shared__ float f1s[R2];
    __shared__ int   adjs[R2][CH2];
    __shared__ float f2s[CH2];
    __shared__ float ps[R2][CH2 + 1];
    __shared__ float h2s[CH2 * NCLS];
    __shared__ float ss[R2];

    int t = threadIdx.x;
    int i0 = blockIdx.x * R2;
    if (t < R2) { f1s[t] = g_f1b[i0 + t]; ss[t] = 0.f; }
    int c = t & 15, rmy = t >> 4;
    float acc = 0.f;

    for (int j0 = 0; j0 < NN; j0 += CH2) {
        __syncthreads();
#pragma unroll
        for (int u = 0; u < 4; u++) {
            int idx = t + u * 256;
            int r = idx >> 6, jj = idx & 63;
            adjs[r][jj] = adj[(i0 + r) * NN + j0 + jj];
        }
        if (t < CH2) f2s[t] = g_f2b[j0 + t];
#pragma unroll
        for (int u = 0; u < 4; u++) {
            int idx = t + u * 256;
            h2s[idx] = g_h2[j0 * NCLS + idx];
        }
        __syncthreads();
        {
            int jj = t & 63;
            int grp = t >> 6;
            float f2v = f2s[jj];
#pragma unroll
            for (int it = 0; it < 4; it++) {
                int r = grp * 4 + it;
                float z = f1s[r] + f2v;
                float e = z > 0.f ? z : 0.01f * z;
                float pv = fast_exp(e);
                ps[r][jj] = (adjs[r][jj] != 0 && e != 0.f) ? pv : 0.f;
            }
        }
        __syncthreads();
#pragma unroll 8
        for (int jj = 0; jj < CH2; jj++) {
            acc += ps[rmy][jj] * h2s[jj * NCLS + c];
        }
        if (t < R2) {
            float sp = 0.f;
#pragma unroll
            for (int jj = 0; jj < CH2; jj++) sp += ps[t][jj];
            ss[t] += sp;
        }
    }
    __syncthreads();
    out[(i0 + rmy) * NCLS + c] = acc / ss[rmy];
}

// ---------------- launcher ----------------
extern "C" void kernel_launch(void* const* d_in, const int* in_sizes, int n_in,
                              void* d_out, int out_size) {
    const float* x   = (const float*)d_in[0];
    const int*   adj = (const int*)d_in[1];
    const float* W1  = (const float*)d_in[2];
    const float* a11 = (const float*)d_in[3];
    const float* a21 = (const float*)d_in[4];
    const float* W2  = (const float*)d_in[5];
    const float* a12 = (const float*)d_in[6];
    const float* a22 = (const float*)d_in[7];
    float* out = (float*)d_out;

    k1_gemm<<<dim3(64, 4), 256>>>(x, W1);
    k2_f<<<NN, 256>>>(a11, a21);
    k3_attn1<<<dim3(NN / R1, JSPLIT), 256>>>(adj);
    k3b_combine<<<NN, 256>>>();
    k4_l2<<<NN / 8, 256>>>(W2, a12, a22);
    k5_attn2<<<NN / R2, 256>>>(adj, out);
}